// round 15
// baseline (speedup 1.0000x reference)
#include <cuda_runtime.h>
#include <cuda_fp16.h>
#include <math_constants.h>
#include <cstdint>

#define NN 25600
#define EE 409600
#define GB 8
#define FF 7
#define HH 300
#define LL 100

// ---- GEMM smem layout: A single fp16 plane, B hi/lo double-buffered ----
#define T_AF   0        // A fp16 [128 rows][64 k], 128B rows, SW128
#define T_BH0  16384
#define T_BL0  32768
#define T_BH1  49152
#define T_BL1  65536
#define SMEM_GEMM 81920

// ---------------- scratch (static device globals; no runtime allocation) ----
__device__ float    g_P[NN * HH];
__device__ float    g_Q[NN * HH];
__device__ unsigned short g_Af[(size_t)EE * 320];   // edge-feature fp16 plane
__device__ unsigned short g_h2f[(size_t)EE * 320];  // h2 fp16 plane (padded)
__device__ float    g_node[NN * LL];
__device__ float    g_pooled[GB * 3 * LL];
// pre-split / transposed / padded weights: B[n][k] = W[k][n], rows padded to 320
__device__ __half g_W2h[2][3 * 128 * 320];
__device__ __half g_W2l[2][3 * 128 * 320];
__device__ __half g_W3h[2][128 * 320];
__device__ __half g_W3l[2][128 * 320];

// ---------------- PTX helpers (baseline compute_103 instructions only) ------
__device__ __forceinline__ uint32_t smem_u32(const void* p) {
    uint32_t a;
    asm("{ .reg .u64 t; cvta.to.shared.u64 t, %1; cvt.u32.u64 %0, t; }"
        : "=r"(a) : "l"(p));
    return a;
}
__device__ __forceinline__ uint32_t sw128(uint32_t o) {
    return o ^ ((o >> 3) & 0x70);
}
// cvt.rn.f16x2.f32 d, a, b : d.hi = f16(a), d.lo = f16(b)
__device__ __forceinline__ uint32_t f16pack(float hi, float lo) {
    uint32_t r;
    asm("cvt.rn.f16x2.f32 %0, %1, %2;" : "=r"(r) : "f"(hi), "f"(lo));
    return r;
}
__device__ __forceinline__ void ldsm4(uint32_t addr, uint32_t* r) {
    asm volatile("ldmatrix.sync.aligned.m8n8.x4.shared.b16 {%0,%1,%2,%3}, [%4];"
                 : "=r"(r[0]), "=r"(r[1]), "=r"(r[2]), "=r"(r[3]) : "r"(addr));
}
__device__ __forceinline__ void mma16816(float* d, const uint32_t* a,
                                         uint32_t b0, uint32_t b1) {
    asm volatile(
        "mma.sync.aligned.m16n8k16.row.col.f32.f16.f16.f32 "
        "{%0,%1,%2,%3}, {%4,%5,%6,%7}, {%8,%9}, {%0,%1,%2,%3};"
        : "+f"(d[0]), "+f"(d[1]), "+f"(d[2]), "+f"(d[3])
        : "r"(a[0]), "r"(a[1]), "r"(a[2]), "r"(a[3]), "r"(b0), "r"(b1));
}
__device__ __forceinline__ void cpa16(uint32_t dst, const void* src) {
    asm volatile("cp.async.cg.shared.global [%0], [%1], 16;" :: "r"(dst), "l"(src));
}
__device__ __forceinline__ void cpa_commit() {
    asm volatile("cp.async.commit_group;");
}
__device__ __forceinline__ void cpa_wait1() {
    asm volatile("cp.async.wait_group 1;");
}
__device__ __forceinline__ void cpa_wait0() {
    asm volatile("cp.async.wait_group 0;");
}

// ---------------------------------------------------------------------------
// split weights into fp16 hi/lo planes, transposed to B[n][k], padded to 320.
__global__ void split_w(const float* __restrict__ W,
                        __half* __restrict__ oh,
                        __half* __restrict__ ol,
                        int K, int Ncols, int rows_per_slab, int valid) {
    int b = blockIdx.x;
    int slab = b / rows_per_slab;
    int n_local = b - slab * rows_per_slab;
    int k = threadIdx.x;
    int n = slab * valid + n_local;
    float v = 0.f;
    if (n_local < valid && k < K && n < Ncols) v = W[k * Ncols + n];
    __half h = __float2half_rn(v);
    __half l = __float2half_rn(v - __half2float(h));
    oh[b * 320 + k] = h;
    ol[b * 320 + k] = l;
}

// ---------------------------------------------------------------------------
// front: per-node first MLP layer, exploiting linearity of concat([x_i, x_j-x_i]).
__global__ void front_kernel(const float* __restrict__ xin, int K,
                             const float* __restrict__ W,
                             const float* __restrict__ b,
                             int from_node) {
    __shared__ float xs[16 * 100];
    const float* __restrict__ x = from_node ? g_node : xin;
    int n0 = blockIdx.x * 16;
    int j = threadIdx.x;
    for (int i = threadIdx.x; i < 16 * K; i += 300)
        xs[i] = x[n0 * K + i];
    __syncthreads();

    float accP[16], accQ[16];
    float bj = b[j];
#pragma unroll
    for (int r = 0; r < 16; r++) { accP[r] = bj; accQ[r] = 0.f; }
    for (int k = 0; k < K; k++) {
        float wa = W[k * HH + j];
        float wb = W[(K + k) * HH + j];
        float d = wa - wb;
#pragma unroll
        for (int r = 0; r < 16; r++) {
            float xv = xs[r * K + k];
            accP[r] = fmaf(xv, d, accP[r]);
            accQ[r] = fmaf(xv, wb, accQ[r]);
        }
    }
#pragma unroll
    for (int r = 0; r < 16; r++) {
        g_P[(n0 + r) * HH + j] = accP[r];
        g_Q[(n0 + r) * HH + j] = accQ[r];
    }
}

// ---------------------------------------------------------------------------
// edge_feat: materialize per-edge fp16 plane ONCE:
//   A[e, k] = fp16(relu(P[dst(e), k] + Q[src(e), k])), pad to 320.
__global__ __launch_bounds__(256) void edge_feat(const int* __restrict__ src) {
    __shared__ int s_src[128];
    int tid = threadIdx.x;
    int row0 = blockIdx.x * 128;
    int n0 = blockIdx.x * 8;
    if (tid < 128) s_src[tid] = src[row0 + tid];
    __syncthreads();

    for (int i = tid; i < 128 * 80; i += 256) {
        int row = i / 80, g = i - row * 80;  // g = float4 group, k = 4g
        int k = g * 4;
        uint32_t h01 = 0, h23 = 0;
        if (g < 75) {                        // 300/4 = 75 exactly
            float4 p = *(const float4*)&g_P[(n0 + (row >> 4)) * HH + k];
            float4 q = *(const float4*)&g_Q[s_src[row] * HH + k];
            h01 = f16pack(fmaxf(p.y + q.y, 0.f), fmaxf(p.x + q.x, 0.f));
            h23 = f16pack(fmaxf(p.w + q.w, 0.f), fmaxf(p.z + q.z, 0.f));
        }
        *(uint2*)&g_Af[(size_t)(row0 + row) * 320 + k] = make_uint2(h01, h23);
    }
}

// ---------------------------------------------------------------------------
// cp.async fill of one 64-k chunk of a single fp16 plane (128 rows x 128 B)
// into an SW128-swizzled smem tile.
__device__ __forceinline__ void cpa_plane(uint32_t dst_base,
                                          const unsigned short* p,
                                          size_t row_base, int k0, int tid) {
#pragma unroll
    for (int i = tid; i < 1024; i += 256) {
        int row = i >> 3, u = i & 7;
        const unsigned short* s = p + row_base + (size_t)row * 320 + k0 + u * 8;
        cpa16(dst_base + sw128((uint32_t)(row * 128 + u * 16)), s);
    }
}

// Core warp-MMA over one staged 64-k chunk: A fp16 single plane, B hi+lo.
__device__ __forceinline__ void mma_chunk(uint32_t sb, uint32_t bh, uint32_t bl,
                                          int arow, int akb, int bn, int bkb,
                                          float acc[2][8][4]) {
#pragma unroll
    for (int s = 0; s < 4; s++) {
        uint32_t af[2][4];
#pragma unroll
        for (int mt = 0; mt < 2; mt++) {
            uint32_t off = sw128((uint32_t)((arow + mt * 16) * 128 + akb + s * 32));
            ldsm4(sb + T_AF + off, af[mt]);
        }
#pragma unroll
        for (int p = 0; p < 4; p++) {
            uint32_t bb[4];
            uint32_t off = sw128((uint32_t)((bn + p * 16) * 128 + bkb + s * 32));
            ldsm4(bh + off, bb);
#pragma unroll
            for (int mt = 0; mt < 2; mt++) {
                mma16816(acc[mt][2 * p + 0], af[mt], bb[0], bb[1]);
                mma16816(acc[mt][2 * p + 1], af[mt], bb[2], bb[3]);
            }
        }
#pragma unroll
        for (int p = 0; p < 4; p++) {
            uint32_t bb[4];
            uint32_t off = sw128((uint32_t)((bn + p * 16) * 128 + bkb + s * 32));
            ldsm4(bl + off, bb);
#pragma unroll
            for (int mt = 0; mt < 2; mt++) {
                mma16816(acc[mt][2 * p + 0], af[mt], bb[0], bb[1]);
                mma16816(acc[mt][2 * p + 1], af[mt], bb[2], bb[3]);
            }
        }
    }
}

// ---------------------------------------------------------------------------
// gemm_mid_mma: h2[128 edges, 100-col slab] = relu(A @ W2 + b2), fp16 2-pass.
__global__ __launch_bounds__(256, 2)
void gemm_mid_mma(const __half* __restrict__ Bh_g,
                  const __half* __restrict__ Bl_g,
                  const float* __restrict__ bias) {
    extern __shared__ char smem[];
    uint32_t sb = smem_u32(smem);
    int tid = threadIdx.x, wid = tid >> 5, lane = tid & 31;
    int mw = wid & 3, nw = wid >> 2;
    int slab = blockIdx.x;
    int row0 = blockIdx.y * 128;
    size_t arow_base = (size_t)row0 * 320;

    const unsigned short* bhp = (const unsigned short*)(Bh_g + slab * (128 * 320));
    const unsigned short* blp = (const unsigned short*)(Bl_g + slab * (128 * 320));

    float acc[2][8][4];
#pragma unroll
    for (int mt = 0; mt < 2; mt++)
#pragma unroll
        for (int nt = 0; nt < 8; nt++)
#pragma unroll
            for (int e = 0; e < 4; e++) acc[mt][nt][e] = 0.f;

    int arow = mw * 32 + (lane & 15);
    int akb = (lane >> 4) * 16;
    int bn = nw * 64 + (lane & 7) + ((lane >> 4) << 3);
    int bkb = ((lane >> 3) & 1) * 16;

    // prologue: B(0) into buf0
    cpa_plane(sb + T_BH0, bhp, 0, 0, tid);
    cpa_plane(sb + T_BL0, blp, 0, 0, tid);
    cpa_commit();

    for (int ch = 0; ch < 5; ch++) {
        int k0 = ch * 64;
        cpa_plane(sb + T_AF, g_Af, arow_base, k0, tid);
        cpa_commit();
        if (ch < 4) {
            int nb = (ch + 1) & 1;
            cpa_plane(sb + (nb ? T_BH1 : T_BH0), bhp, 0, k0 + 64, tid);
            cpa_plane(sb + (nb ? T_BL1 : T_BL0), blp, 0, k0 + 64, tid);
            cpa_commit();
            cpa_wait1();          // A(ch), B(ch) done; B(ch+1) in flight
        } else {
            cpa_wait0();
        }
        __syncthreads();
        int cb = ch & 1;
        mma_chunk(sb, sb + (cb ? T_BH1 : T_BH0), sb + (cb ? T_BL1 : T_BL0),
                  arow, akb, bn, bkb, acc);
        __syncthreads();
    }

    // epilogue: bias + relu + fp16 -> h2 plane (stride 320; slab2 zeros k-pad)
    unsigned short* stage = (unsigned short*)smem;   // [128][104]
#pragma unroll
    for (int mt = 0; mt < 2; mt++)
#pragma unroll
        for (int nt = 0; nt < 8; nt++) {
            int c = nw * 64 + nt * 8 + (lane & 3) * 2;
            int r0 = mw * 32 + mt * 16 + (lane >> 2);
#pragma unroll
            for (int e = 0; e < 4; e++) {
                int cc = c + (e & 1);
                int rr = (e < 2) ? r0 : r0 + 8;
                if (cc < 100) {
                    float v = fmaxf(acc[mt][nt][e] + bias[slab * 100 + cc], 0.f);
                    stage[rr * 104 + cc] = __half_as_ushort(__float2half_rn(v));
                }
            }
        }
    __syncthreads();
    for (int i = tid; i < 12800; i += 256) {
        int row = i / 100, c = i - row * 100;
        g_h2f[(size_t)(row0 + row) * 320 + slab * 100 + c] = stage[row * 104 + c];
    }
    if (slab == 2) {  // zero the k-pad [300,320) once per row block
        for (int i = tid; i < 128 * 20; i += 256) {
            int row = i / 20, c = i - row * 20;
            g_h2f[(size_t)(row0 + row) * 320 + 300 + c] = 0;
        }
    }
}

// ---------------------------------------------------------------------------
// gemm_out_mma: h3 = h2 @ W3 (fp16 2-pass), fused max over 16-edge groups,
// +b3, relu -> g_node.
__global__ __launch_bounds__(256, 2)
void gemm_out_mma(const __half* __restrict__ Bh_g,
                  const __half* __restrict__ Bl_g,
                  const float* __restrict__ bias) {
    extern __shared__ char smem[];
    uint32_t sb = smem_u32(smem);
    int tid = threadIdx.x, wid = tid >> 5, lane = tid & 31;
    int mw = wid & 3, nw = wid >> 2;
    int row0 = blockIdx.x * 128;
    int n0 = blockIdx.x * 8;
    size_t arow_base = (size_t)row0 * 320;

    const unsigned short* bhp = (const unsigned short*)Bh_g;
    const unsigned short* blp = (const unsigned short*)Bl_g;

    float acc[2][8][4];
#pragma unroll
    for (int mt = 0; mt < 2; mt++)
#pragma unroll
        for (int nt = 0; nt < 8; nt++)
#pragma unroll
            for (int e = 0; e < 4; e++) acc[mt][nt][e] = 0.f;

    int arow = mw * 32 + (lane & 15);
    int akb = (lane >> 4) * 16;
    int bn = nw * 64 + (lane & 7) + ((lane >> 4) << 3);
    int bkb = ((lane >> 3) & 1) * 16;

    cpa_plane(sb + T_BH0, bhp, 0, 0, tid);
    cpa_plane(sb + T_BL0, blp, 0, 0, tid);
    cpa_commit();

    for (int ch = 0; ch < 5; ch++) {
        int k0 = ch * 64;
        cpa_plane(sb + T_AF, g_h2f, arow_base, k0, tid);
        cpa_commit();
        if (ch < 4) {
            int nb = (ch + 1) & 1;
            cpa_plane(sb + (nb ? T_BH1 : T_BH0), bhp, 0, k0 + 64, tid);
            cpa_plane(sb + (nb ? T_BL1 : T_BL0), blp, 0, k0 + 64, tid);
            cpa_commit();
            cpa_wait1();
        } else {
            cpa_wait0();
        }
        __syncthreads();
        int cb = ch & 1;
        mma_chunk(sb, sb + (cb ? T_BH1 : T_BH0), sb + (cb ? T_BL1 : T_BL0),
                  arow, akb, bn, bkb, acc);
        __syncthreads();
    }

    float* stagef = (float*)smem;        // [128][104]
#pragma unroll
    for (int mt = 0; mt < 2; mt++)
#pragma unroll
        for (int nt = 0; nt < 8; nt++) {
            int c = nw * 64 + nt * 8 + (lane & 3) * 2;
            int r0 = mw * 32 + mt * 16 + (lane >> 2);
#pragma unroll
            for (int e = 0; e < 4; e++) {
                int cc = c + (e & 1);
                int rr = (e < 2) ? r0 : r0 + 8;
                if (cc < 100) stagef[rr * 104 + cc] = acc[mt][nt][e];
            }
        }
    __syncthreads();
    for (int i = tid; i < 800; i += 256) {
        int n = i / 100, c = i - n * 100;
        float m = -CUDART_INF_F;
#pragma unroll
        for (int rr = 0; rr < 16; rr++)
            m = fmaxf(m, stagef[(n * 16 + rr) * 104 + c]);
        g_node[(n0 + n) * LL + c] = fmaxf(m + bias[c], 0.f);
    }
}

// ---------------------------------------------------------------------------
__global__ void pool_kernel() {
    __shared__ float ssum[8][100];
    __shared__ float smax[8][100];
    int g = blockIdx.x;
    int col = threadIdx.x % 100;
    int part = threadIdx.x / 100;
    float s = 0.f, m = -CUDART_INF_F;
    int base = g * 3200 + part * 400;
    for (int n = 0; n < 400; n++) {
        float v = g_node[(base + n) * LL + col];
        s += v;
        m = fmaxf(m, v);
    }
    ssum[part][col] = s;
    smax[part][col] = m;
    __syncthreads();
    if (part == 0) {
        for (int p = 1; p < 8; p++) {
            s += ssum[p][col];
            m = fmaxf(m, smax[p][col]);
        }
        g_pooled[g * 300 + col] = s;
        g_pooled[g * 300 + 100 + col] = s / 3200.0f;
        g_pooled[g * 300 + 200 + col] = m;
    }
}

__global__ void final_kernel(const float* __restrict__ W1, const float* __restrict__ b1,
                             const float* __restrict__ W2, const float* __restrict__ b2,
                             const float* __restrict__ W3, const float* __restrict__ b3,
                             float* __restrict__ out) {
    __shared__ float sp[GB * 300];
    __shared__ float t1[GB * 100];
    int j = threadIdx.x;
    for (int i = j; i < GB * 300; i += blockDim.x) sp[i] = g_pooled[i];
    __syncthreads();
    if (j < 100) {
        float acc[GB];
#pragma unroll
        for (int r = 0; r < GB; r++) acc[r] = b1[j];
        for (int k = 0; k < 300; k++) {
            float w = W1[k * 100 + j];
#pragma unroll
            for (int r = 0; r < GB; r++) acc[r] = fmaf(sp[r * 300 + k], w, acc[r]);
        }
#pragma unroll
        for (int r = 0; r < GB; r++) t1[r * 100 + j] = fmaxf(acc[r], 0.f);
    }
    __syncthreads();
    float acc2[GB];
    if (j < 100) {
#pragma unroll
        for (int r = 0; r < GB; r++) acc2[r] = b2[j];
        for (int k = 0; k < 100; k++) {
            float w = W2[k * 100 + j];
#pragma unroll
            for (int r = 0; r < GB; r++) acc2[r] = fmaf(t1[r * 100 + k], w, acc2[r]);
        }
    }
    __syncthreads();
    if (j < 100) {
#pragma unroll
        for (int r = 0; r < GB; r++) sp[r * 100 + j] = fmaxf(acc2[r], 0.f);
    }
    __syncthreads();
    if (j < GB) {
        float s = b3[0];
        for (int k = 0; k < 100; k++) s = fmaf(sp[j * 100 + k], W3[k], s);
        out[j] = s;
    }
}

// ---------------------------------------------------------------------------
extern "C" void kernel_launch(void* const* d_in, const int* in_sizes, int n_in,
                              void* d_out, int out_size) {
    const float* x     = (const float*)d_in[0];
    const int*   eidx  = (const int*)d_in[1];
    const float* l0_W1 = (const float*)d_in[3];
    const float* l0_b1 = (const float*)d_in[4];
    const float* l0_W2 = (const float*)d_in[5];
    const float* l0_b2 = (const float*)d_in[6];
    const float* l0_W3 = (const float*)d_in[7];
    const float* l0_b3 = (const float*)d_in[8];
    const float* l1_W1 = (const float*)d_in[9];
    const float* l1_b1 = (const float*)d_in[10];
    const float* l1_W2 = (const float*)d_in[11];
    const float* l1_b2 = (const float*)d_in[12];
    const float* l1_W3 = (const float*)d_in[13];
    const float* l1_b3 = (const float*)d_in[14];
    const float* lin_W1 = (const float*)d_in[15];
    const float* lin_b1 = (const float*)d_in[16];
    const float* lin_W2 = (const float*)d_in[17];
    const float* lin_b2 = (const float*)d_in[18];
    const float* lin_W3 = (const float*)d_in[19];
    const float* lin_b3 = (const float*)d_in[20];

    const int* src = eidx;

    cudaFuncSetAttribute(gemm_mid_mma, cudaFuncAttributeMaxDynamicSharedMemorySize, SMEM_GEMM);
    cudaFuncSetAttribute(gemm_out_mma, cudaFuncAttributeMaxDynamicSharedMemorySize, SMEM_GEMM);

    __half *w2h0, *w2l0, *w2h1, *w2l1, *w3h0, *w3l0, *w3h1, *w3l1;
    cudaGetSymbolAddress((void**)&w2h0, g_W2h);
    cudaGetSymbolAddress((void**)&w2l0, g_W2l);
    cudaGetSymbolAddress((void**)&w3h0, g_W3h);
    cudaGetSymbolAddress((void**)&w3l0, g_W3l);
    w2h1 = w2h0 + 3 * 128 * 320; w2l1 = w2l0 + 3 * 128 * 320;
    w3h1 = w3h0 + 128 * 320;     w3l1 = w3l0 + 128 * 320;

    // weight prep (tiny): W2 -> 3 slabs x 128 rows (100 valid), W3 -> 128 rows
    split_w<<<3 * 128, 320>>>(l0_W2, w2h0, w2l0, 300, 300, 128, 100);
    split_w<<<128, 320>>>(l0_W3, w3h0, w3l0, 300, 100, 128, 100);
    split_w<<<3 * 128, 320>>>(l1_W2, w2h1, w2l1, 300, 300, 128, 100);
    split_w<<<128, 320>>>(l1_W3, w3h1, w3l1, 300, 100, 128, 100);

    // ---- layer 0 ----
    front_kernel<<<NN / 16, 300>>>(x, FF, l0_W1, l0_b1, 0);
    edge_feat<<<EE / 128, 256>>>(src);
    gemm_mid_mma<<<dim3(3, EE / 128), 256, SMEM_GEMM>>>(w2h0, w2l0, l0_b2);
    gemm_out_mma<<<EE / 128, 256, SMEM_GEMM>>>(w3h0, w3l0, l0_b3);
    // ---- layer 1 ----
    front_kernel<<<NN / 16, 300>>>(nullptr, LL, l1_W1, l1_b1, 1);
    edge_feat<<<EE / 128, 256>>>(src);
    gemm_mid_mma<<<dim3(3, EE / 128), 256, SMEM_GEMM>>>(w2h1, w2l1, l1_b2);
    gemm_out_mma<<<EE / 128, 256, SMEM_GEMM>>>(w3h1, w3l1, l1_b3);
    // ---- pooling + head ----
    pool_kernel<<<GB, 800>>>();
    final_kernel<<<1, 128>>>(lin_W1, lin_b1, lin_W2, lin_b2, lin_W3, lin_b3,
                             (float*)d_out);
}

// round 17
// speedup vs baseline: 2.0147x; 2.0147x over previous
#include <cuda_runtime.h>
#include <cuda_fp16.h>
#include <math_constants.h>
#include <cstdint>

#define NN 25600
#define EE 409600
#define GB 8
#define FF 7
#define HH 300
#define LL 100

// ---- GEMM smem layout: A fp16 plane single-buffer, B fp16 double-buffer ----
#define T_AF   0        // A fp16 [128 rows][64 k], 128B rows, SW128
#define T_B0   16384
#define T_B1   32768
// 48 KB of tiles, but the gemm_out epilogue overlays float[128][104] = 53248 B.
#define SMEM_GEMM 53248

// ---------------- scratch (static device globals; no runtime allocation) ----
__device__ float    g_P[NN * HH];
__device__ float    g_Q[NN * HH];
__device__ unsigned short g_Af[(size_t)EE * 320];   // edge-feature fp16 plane
__device__ unsigned short g_h2f[(size_t)EE * 320];  // h2 fp16 plane (padded)
__device__ float    g_node[NN * LL];
__device__ float    g_pooled[GB * 3 * LL];
// fp16 weights, transposed to B[n][k] = W[k][n], rows padded to 320
__device__ __half g_W2f[2][3 * 128 * 320];
__device__ __half g_W3f[2][128 * 320];

// ---------------- PTX helpers (baseline compute_103 instructions only) ------
__device__ __forceinline__ uint32_t smem_u32(const void* p) {
    uint32_t a;
    asm("{ .reg .u64 t; cvta.to.shared.u64 t, %1; cvt.u32.u64 %0, t; }"
        : "=r"(a) : "l"(p));
    return a;
}
__device__ __forceinline__ uint32_t sw128(uint32_t o) {
    return o ^ ((o >> 3) & 0x70);
}
// cvt.rn.f16x2.f32 d, a, b : d.hi = f16(a), d.lo = f16(b)
__device__ __forceinline__ uint32_t f16pack(float hi, float lo) {
    uint32_t r;
    asm("cvt.rn.f16x2.f32 %0, %1, %2;" : "=r"(r) : "f"(hi), "f"(lo));
    return r;
}
__device__ __forceinline__ void ldsm4(uint32_t addr, uint32_t* r) {
    asm volatile("ldmatrix.sync.aligned.m8n8.x4.shared.b16 {%0,%1,%2,%3}, [%4];"
                 : "=r"(r[0]), "=r"(r[1]), "=r"(r[2]), "=r"(r[3]) : "r"(addr));
}
__device__ __forceinline__ void mma16816(float* d, const uint32_t* a,
                                         uint32_t b0, uint32_t b1) {
    asm volatile(
        "mma.sync.aligned.m16n8k16.row.col.f32.f16.f16.f32 "
        "{%0,%1,%2,%3}, {%4,%5,%6,%7}, {%8,%9}, {%0,%1,%2,%3};"
        : "+f"(d[0]), "+f"(d[1]), "+f"(d[2]), "+f"(d[3])
        : "r"(a[0]), "r"(a[1]), "r"(a[2]), "r"(a[3]), "r"(b0), "r"(b1));
}
__device__ __forceinline__ void cpa16(uint32_t dst, const void* src) {
    asm volatile("cp.async.cg.shared.global [%0], [%1], 16;" :: "r"(dst), "l"(src));
}
__device__ __forceinline__ void cpa_commit() {
    asm volatile("cp.async.commit_group;");
}
__device__ __forceinline__ void cpa_wait1() {
    asm volatile("cp.async.wait_group 1;");
}
__device__ __forceinline__ void cpa_wait0() {
    asm volatile("cp.async.wait_group 0;");
}

// ---------------------------------------------------------------------------
// convert weights to fp16, transposed to B[n][k], padded to 320.
__global__ void conv_w(const float* __restrict__ W,
                       __half* __restrict__ oh,
                       int K, int Ncols, int rows_per_slab, int valid) {
    int b = blockIdx.x;
    int slab = b / rows_per_slab;
    int n_local = b - slab * rows_per_slab;
    int k = threadIdx.x;
    int n = slab * valid + n_local;
    float v = 0.f;
    if (n_local < valid && k < K && n < Ncols) v = W[k * Ncols + n];
    oh[b * 320 + k] = __float2half_rn(v);
}

// ---------------------------------------------------------------------------
// front: per-node first MLP layer, exploiting linearity of concat([x_i, x_j-x_i]).
__global__ void front_kernel(const float* __restrict__ xin, int K,
                             const float* __restrict__ W,
                             const float* __restrict__ b,
                             int from_node) {
    __shared__ float xs[16 * 100];
    const float* __restrict__ x = from_node ? g_node : xin;
    int n0 = blockIdx.x * 16;
    int j = threadIdx.x;
    for (int i = threadIdx.x; i < 16 * K; i += 300)
        xs[i] = x[n0 * K + i];
    __syncthreads();

    float accP[16], accQ[16];
    float bj = b[j];
#pragma unroll
    for (int r = 0; r < 16; r++) { accP[r] = bj; accQ[r] = 0.f; }
    for (int k = 0; k < K; k++) {
        float wa = W[k * HH + j];
        float wb = W[(K + k) * HH + j];
        float d = wa - wb;
#pragma unroll
        for (int r = 0; r < 16; r++) {
            float xv = xs[r * K + k];
            accP[r] = fmaf(xv, d, accP[r]);
            accQ[r] = fmaf(xv, wb, accQ[r]);
        }
    }
#pragma unroll
    for (int r = 0; r < 16; r++) {
        g_P[(n0 + r) * HH + j] = accP[r];
        g_Q[(n0 + r) * HH + j] = accQ[r];
    }
}

// ---------------------------------------------------------------------------
// edge_feat: materialize per-edge fp16 plane ONCE:
//   A[e, k] = fp16(relu(P[dst(e), k] + Q[src(e), k])), pad to 320.
__global__ __launch_bounds__(256) void edge_feat(const int* __restrict__ src) {
    __shared__ int s_src[128];
    int tid = threadIdx.x;
    int row0 = blockIdx.x * 128;
    int n0 = blockIdx.x * 8;
    if (tid < 128) s_src[tid] = src[row0 + tid];
    __syncthreads();

    for (int i = tid; i < 128 * 80; i += 256) {
        int row = i / 80, g = i - row * 80;  // g = float4 group, k = 4g
        int k = g * 4;
        uint32_t h01 = 0, h23 = 0;
        if (g < 75) {                        // 300/4 = 75 exactly
            float4 p = *(const float4*)&g_P[(n0 + (row >> 4)) * HH + k];
            float4 q = *(const float4*)&g_Q[s_src[row] * HH + k];
            h01 = f16pack(fmaxf(p.y + q.y, 0.f), fmaxf(p.x + q.x, 0.f));
            h23 = f16pack(fmaxf(p.w + q.w, 0.f), fmaxf(p.z + q.z, 0.f));
        }
        *(uint2*)&g_Af[(size_t)(row0 + row) * 320 + k] = make_uint2(h01, h23);
    }
}

// ---------------------------------------------------------------------------
// cp.async fill of one 64-k chunk of a single fp16 plane (128 rows x 128 B)
// into an SW128-swizzled smem tile.
__device__ __forceinline__ void cpa_plane(uint32_t dst_base,
                                          const unsigned short* p,
                                          size_t row_base, int k0, int tid) {
#pragma unroll
    for (int i = tid; i < 1024; i += 256) {
        int row = i >> 3, u = i & 7;
        const unsigned short* s = p + row_base + (size_t)row * 320 + k0 + u * 8;
        cpa16(dst_base + sw128((uint32_t)(row * 128 + u * 16)), s);
    }
}

// Core warp-MMA over one staged 64-k chunk: pure fp16, single pass.
__device__ __forceinline__ void mma_chunk(uint32_t sb, uint32_t bbuf,
                                          int arow, int akb, int bn, int bkb,
                                          float acc[2][8][4]) {
#pragma unroll
    for (int s = 0; s < 4; s++) {
        uint32_t af[2][4];
#pragma unroll
        for (int mt = 0; mt < 2; mt++) {
            uint32_t off = sw128((uint32_t)((arow + mt * 16) * 128 + akb + s * 32));
            ldsm4(sb + T_AF + off, af[mt]);
        }
#pragma unroll
        for (int p = 0; p < 4; p++) {
            uint32_t bb[4];
            uint32_t off = sw128((uint32_t)((bn + p * 16) * 128 + bkb + s * 32));
            ldsm4(bbuf + off, bb);
#pragma unroll
            for (int mt = 0; mt < 2; mt++) {
                mma16816(acc[mt][2 * p + 0], af[mt], bb[0], bb[1]);
                mma16816(acc[mt][2 * p + 1], af[mt], bb[2], bb[3]);
            }
        }
    }
}

// ---------------------------------------------------------------------------
// gemm_mid_mma: h2[128 edges, 100-col slab] = relu(A @ W2 + b2), fp16 1-pass.
__global__ __launch_bounds__(256, 2)
void gemm_mid_mma(const __half* __restrict__ B_g,
                  const float* __restrict__ bias) {
    extern __shared__ char smem[];
    uint32_t sb = smem_u32(smem);
    int tid = threadIdx.x, wid = tid >> 5, lane = tid & 31;
    int mw = wid & 3, nw = wid >> 2;
    int slab = blockIdx.x;
    int row0 = blockIdx.y * 128;
    size_t arow_base = (size_t)row0 * 320;

    const unsigned short* bp = (const unsigned short*)(B_g + slab * (128 * 320));

    float acc[2][8][4];
#pragma unroll
    for (int mt = 0; mt < 2; mt++)
#pragma unroll
        for (int nt = 0; nt < 8; nt++)
#pragma unroll
            for (int e = 0; e < 4; e++) acc[mt][nt][e] = 0.f;

    int arow = mw * 32 + (lane & 15);
    int akb = (lane >> 4) * 16;
    int bn = nw * 64 + (lane & 7) + ((lane >> 4) << 3);
    int bkb = ((lane >> 3) & 1) * 16;

    // prologue: B(0) into buf0
    cpa_plane(sb + T_B0, bp, 0, 0, tid);
    cpa_commit();

    for (int ch = 0; ch < 5; ch++) {
        int k0 = ch * 64;
        cpa_plane(sb + T_AF, g_Af, arow_base, k0, tid);
        cpa_commit();
        if (ch < 4) {
            int nb = (ch + 1) & 1;
            cpa_plane(sb + (nb ? T_B1 : T_B0), bp, 0, k0 + 64, tid);
            cpa_commit();
            cpa_wait1();          // A(ch), B(ch) done; B(ch+1) in flight
        } else {
            cpa_wait0();
        }
        __syncthreads();
        int cb = ch & 1;
        mma_chunk(sb, sb + (cb ? T_B1 : T_B0), arow, akb, bn, bkb, acc);
        __syncthreads();
    }

    // epilogue: bias + relu + fp16 -> h2 plane (stride 320; slab2 zeros k-pad)
    unsigned short* stage = (unsigned short*)smem;   // [128][104] u16 = 26624 B
#pragma unroll
    for (int mt = 0; mt < 2; mt++)
#pragma unroll
        for (int nt = 0; nt < 8; nt++) {
            int c = nw * 64 + nt * 8 + (lane & 3) * 2;
            int r0 = mw * 32 + mt * 16 + (lane >> 2);
#pragma unroll
            for (int e = 0; e < 4; e++) {
                int cc = c + (e & 1);
                int rr = (e < 2) ? r0 : r0 + 8;
                if (cc < 100) {
                    float v = fmaxf(acc[mt][nt][e] + bias[slab * 100 + cc], 0.f);
                    stage[rr * 104 + cc] = __half_as_ushort(__float2half_rn(v));
                }
            }
        }
    __syncthreads();
    for (int i = tid; i < 12800; i += 256) {
        int row = i / 100, c = i - row * 100;
        g_h2f[(size_t)(row0 + row) * 320 + slab * 100 + c] = stage[row * 104 + c];
    }
    if (slab == 2) {  // zero the k-pad [300,320) once per row block
        for (int i = tid; i < 128 * 20; i += 256) {
            int row = i / 20, c = i - row * 20;
            g_h2f[(size_t)(row0 + row) * 320 + 300 + c] = 0;
        }
    }
}

// ---------------------------------------------------------------------------
// gemm_out_mma: h3 = h2 @ W3 (fp16 1-pass), fused max over 16-edge groups,
// +b3, relu -> g_node.
__global__ __launch_bounds__(256, 2)
void gemm_out_mma(const __half* __restrict__ B_g,
                  const float* __restrict__ bias) {
    extern __shared__ char smem[];
    uint32_t sb = smem_u32(smem);
    int tid = threadIdx.x, wid = tid >> 5, lane = tid & 31;
    int mw = wid & 3, nw = wid >> 2;
    int row0 = blockIdx.x * 128;
    int n0 = blockIdx.x * 8;
    size_t arow_base = (size_t)row0 * 320;

    const unsigned short* bp = (const unsigned short*)B_g;

    float acc[2][8][4];
#pragma unroll
    for (int mt = 0; mt < 2; mt++)
#pragma unroll
        for (int nt = 0; nt < 8; nt++)
#pragma unroll
            for (int e = 0; e < 4; e++) acc[mt][nt][e] = 0.f;

    int arow = mw * 32 + (lane & 15);
    int akb = (lane >> 4) * 16;
    int bn = nw * 64 + (lane & 7) + ((lane >> 4) << 3);
    int bkb = ((lane >> 3) & 1) * 16;

    cpa_plane(sb + T_B0, bp, 0, 0, tid);
    cpa_commit();

    for (int ch = 0; ch < 5; ch++) {
        int k0 = ch * 64;
        cpa_plane(sb + T_AF, g_h2f, arow_base, k0, tid);
        cpa_commit();
        if (ch < 4) {
            int nb = (ch + 1) & 1;
            cpa_plane(sb + (nb ? T_B1 : T_B0), bp, 0, k0 + 64, tid);
            cpa_commit();
            cpa_wait1();
        } else {
            cpa_wait0();
        }
        __syncthreads();
        int cb = ch & 1;
        mma_chunk(sb, sb + (cb ? T_B1 : T_B0), arow, akb, bn, bkb, acc);
        __syncthreads();
    }

    float* stagef = (float*)smem;        // [128][104] f32 = 53248 B (fits SMEM_GEMM)
#pragma unroll
    for (int mt = 0; mt < 2; mt++)
#pragma unroll
        for (int nt = 0; nt < 8; nt++) {
            int c = nw * 64 + nt * 8 + (lane & 3) * 2;
            int r0 = mw * 32 + mt * 16 + (lane >> 2);
#pragma unroll
            for (int e = 0; e < 4; e++) {
                int cc = c + (e & 1);
                int rr = (e < 2) ? r0 : r0 + 8;
                if (cc < 100) stagef[rr * 104 + cc] = acc[mt][nt][e];
            }
        }
    __syncthreads();
    for (int i = tid; i < 800; i += 256) {
        int n = i / 100, c = i - n * 100;
        float m = -CUDART_INF_F;
#pragma unroll
        for (int rr = 0; rr < 16; rr++)
            m = fmaxf(m, stagef[(n * 16 + rr) * 104 + c]);
        g_node[(n0 + n) * LL + c] = fmaxf(m + bias[c], 0.f);
    }
}

// ---------------------------------------------------------------------------
__global__ void pool_kernel() {
    __shared__ float ssum[8][100];
    __shared__ float smax[8][100];
    int g = blockIdx.x;
    int col = threadIdx.x % 100;
    int part = threadIdx.x / 100;
    float s = 0.f, m = -CUDART_INF_F;
    int base = g * 3200 + part * 400;
    for (int n = 0; n < 400; n++) {
        float v = g_node[(base + n) * LL + col];
        s += v;
        m = fmaxf(m, v);
    }
    ssum[part][col] = s;
    smax[part][col] = m;
    __syncthreads();
    if (part == 0) {
        for (int p = 1; p < 8; p++) {
            s += ssum[p][col];
            m = fmaxf(m, smax[p][col]);
        }
        g_pooled[g * 300 + col] = s;
        g_pooled[g * 300 + 100 + col] = s / 3200.0f;
        g_pooled[g * 300 + 200 + col] = m;
    }
}

__global__ void final_kernel(const float* __restrict__ W1, const float* __restrict__ b1,
                             const float* __restrict__ W2, const float* __restrict__ b2,
                             const float* __restrict__ W3, const float* __restrict__ b3,
                             float* __restrict__ out) {
    __shared__ float sp[GB * 300];
    __shared__ float t1[GB * 100];
    int j = threadIdx.x;
    for (int i = j; i < GB * 300; i += blockDim.x) sp[i] = g_pooled[i];
    __syncthreads();
    if (j < 100) {
        float acc[GB];
#pragma unroll
        for (int r = 0; r < GB; r++) acc[r] = b1[j];
        for (int k = 0; k < 300; k++) {
            float w = W1[k * 100 + j];
#pragma unroll
            for (int r = 0; r < GB; r++) acc[r] = fmaf(sp[r * 300 + k], w, acc[r]);
        }
#pragma unroll
        for (int r = 0; r < GB; r++) t1[r * 100 + j] = fmaxf(acc[r], 0.f);
    }
    __syncthreads();
    float acc2[GB];
    if (j < 100) {
#pragma unroll
        for (int r = 0; r < GB; r++) acc2[r] = b2[j];
        for (int k = 0; k < 100; k++) {
            float w = W2[k * 100 + j];
#pragma unroll
            for (int r = 0; r < GB; r++) acc2[r] = fmaf(t1[r * 100 + k], w, acc2[r]);
        }
    }
    __syncthreads();
    if (j < 100) {
#pragma unroll
        for (int r = 0; r < GB; r++) sp[r * 100 + j] = fmaxf(acc2[r], 0.f);
    }
    __syncthreads();
    if (j < GB) {
        float s = b3[0];
        for (int k = 0; k < 100; k++) s = fmaf(sp[j * 100 + k], W3[k], s);
        out[j] = s;
    }
}

// ---------------------------------------------------------------------------
extern "C" void kernel_launch(void* const* d_in, const int* in_sizes, int n_in,
                              void* d_out, int out_size) {
    const float* x     = (const float*)d_in[0];
    const int*   eidx  = (const int*)d_in[1];
    const float* l0_W1 = (const float*)d_in[3];
    const float* l0_b1 = (const float*)d_in[4];
    const float* l0_W2 = (const float*)d_in[5];
    const float* l0_b2 = (const float*)d_in[6];
    const float* l0_W3 = (const float*)d_in[7];
    const float* l0_b3 = (const float*)d_in[8];
    const float* l1_W1 = (const float*)d_in[9];
    const float* l1_b1 = (const float*)d_in[10];
    const float* l1_W2 = (const float*)d_in[11];
    const float* l1_b2 = (const float*)d_in[12];
    const float* l1_W3 = (const float*)d_in[13];
    const float* l1_b3 = (const float*)d_in[14];
    const float* lin_W1 = (const float*)d_in[15];
    const float* lin_b1 = (const float*)d_in[16];
    const float* lin_W2 = (const float*)d_in[17];
    const float* lin_b2 = (const float*)d_in[18];
    const float* lin_W3 = (const float*)d_in[19];
    const float* lin_b3 = (const float*)d_in[20];

    const int* src = eidx;

    cudaFuncSetAttribute(gemm_mid_mma, cudaFuncAttributeMaxDynamicSharedMemorySize, SMEM_GEMM);
    cudaFuncSetAttribute(gemm_out_mma, cudaFuncAttributeMaxDynamicSharedMemorySize, SMEM_GEMM);

    __half *w2f0, *w2f1, *w3f0, *w3f1;
    cudaGetSymbolAddress((void**)&w2f0, g_W2f);
    cudaGetSymbolAddress((void**)&w3f0, g_W3f);
    w2f1 = w2f0 + 3 * 128 * 320;
    w3f1 = w3f0 + 128 * 320;

    // weight prep (tiny): W2 -> 3 slabs x 128 rows (100 valid), W3 -> 128 rows
    conv_w<<<3 * 128, 320>>>(l0_W2, w2f0, 300, 300, 128, 100);
    conv_w<<<128, 320>>>(l0_W3, w3f0, 300, 100, 128, 100);
    conv_w<<<3 * 128, 320>>>(l1_W2, w2f1, 300, 300, 128, 100);
    conv_w<<<128, 320>>>(l1_W3, w3f1, 300, 100, 128, 100);

    // ---- layer 0 ----
    front_kernel<<<NN / 16, 300>>>(x, FF, l0_W1, l0_b1, 0);
    edge_feat<<<EE / 128, 256>>>(src);
    gemm_mid_mma<<<dim3(3, EE / 128), 256, SMEM_GEMM>>>(w2f0, l0_b2);
    gemm_out_mma<<<EE / 128, 256, SMEM_GEMM>>>(w3f0, l0_b3);
    // ---- layer 1 ----
    front_kernel<<<NN / 16, 300>>>(nullptr, LL, l1_W1, l1_b1, 1);
    edge_feat<<<EE / 128, 256>>>(src);
    gemm_mid_mma<<<dim3(3, EE / 128), 256, SMEM_GEMM>>>(w2f1, l1_b2);
    gemm_out_mma<<<EE / 128, 256, SMEM_GEMM>>>(w3f1, l1_b3);
    // ---- pooling + head ----
    pool_kernel<<<GB, 800>>>();
    final_kernel<<<1, 128>>>(lin_W1, lin_b1, lin_W2, lin_b2, lin_W3, lin_b3,
                             (float*)d_out);
}